// round 1
// baseline (speedup 1.0000x reference)
#include <cuda_runtime.h>

// Problem: reference softmax acts on a size-1 axis -> alphas == 1.0 everywhere.
// context[b,0,d] = sum_t a[b,t,d]. Pure HBM-bound column-sum of a [128,512,512].

#define B_  128
#define TX_ 512
#define D_  512
#define SPLIT 8
#define T_PER (TX_ / SPLIT)   // 64

// Fixed scratch for deterministic two-pass reduction (no atomics).
__device__ float g_partial[SPLIT * B_ * D_];   // 2 MB

__global__ __launch_bounds__(128) void partial_sum_kernel(const float* __restrict__ a) {
    const int b   = blockIdx.x;
    const int s   = blockIdx.y;
    const int tid = threadIdx.x;                 // 0..127, one float4 of d each

    const float4* base = reinterpret_cast<const float4*>(a)
                         + (size_t)b * TX_ * (D_ / 4);
    float4 acc = make_float4(0.f, 0.f, 0.f, 0.f);
    const int t0 = s * T_PER;

    #pragma unroll 8
    for (int t = 0; t < T_PER; ++t) {
        float4 v = base[(size_t)(t0 + t) * (D_ / 4) + tid];
        acc.x += v.x; acc.y += v.y; acc.z += v.z; acc.w += v.w;
    }

    reinterpret_cast<float4*>(g_partial)[((size_t)s * B_ + b) * (D_ / 4) + tid] = acc;
}

__global__ __launch_bounds__(256) void final_sum_kernel(float* __restrict__ out) {
    const int idx = blockIdx.x * blockDim.x + threadIdx.x;   // 0 .. B_*D_-1
    if (idx >= B_ * D_) return;
    float acc = 0.f;
    #pragma unroll
    for (int s = 0; s < SPLIT; ++s)
        acc += g_partial[s * (B_ * D_) + idx];
    out[idx] = acc;
}

extern "C" void kernel_launch(void* const* d_in, const int* in_sizes, int n_in,
                              void* d_out, int out_size) {
    const float* a = (const float*)d_in[0];   // [B, Tx, D_A] fp32
    float* out = (float*)d_out;               // [B, 1, D_A] fp32 = 65536 elems

    dim3 grid1(B_, SPLIT);
    partial_sum_kernel<<<grid1, 128>>>(a);
    final_sum_kernel<<<(B_ * D_ + 255) / 256, 256>>>(out);
}